// round 8
// baseline (speedup 1.0000x reference)
#include <cuda_runtime.h>
#include <cuda_fp16.h>
#include <cstdint>

#define NNODES 100000
#define DIM    128

// ---------------- scratch (static __device__, no runtime alloc) ----------------
__device__ __half g_lnH[NNODES * DIM];  // normalized x (no affine), fp16
__device__ __half g_AH [NNODES * DIM];  // mean_{(u->v)} ln[u] @ v (fwd), fp16
__device__ __half g_ArH[NNODES * DIM];  // mean_{(u->v)} ln[v] @ u (rev), fp16
__device__ float  g_din [NNODES];       // in-degree  (raw count)
__device__ float  g_dout[NNODES];       // out-degree (raw count)

// ---------------- helpers ----------------
__device__ __forceinline__ void mma_f16(float* c, const uint32_t* a, const uint32_t* b) {
    asm volatile(
        "mma.sync.aligned.m16n8k16.row.col.f32.f16.f16.f32 "
        "{%0,%1,%2,%3}, {%4,%5,%6,%7}, {%8,%9}, {%0,%1,%2,%3};\n"
        : "+f"(c[0]), "+f"(c[1]), "+f"(c[2]), "+f"(c[3])
        : "r"(a[0]), "r"(a[1]), "r"(a[2]), "r"(a[3]), "r"(b[0]), "r"(b[1]));
}

#define LDSM4(R, ADDR) \
    asm volatile("ldmatrix.sync.aligned.m8n8.x4.shared.b16 {%0,%1,%2,%3}, [%4];" \
                 : "=r"((R)[0]), "=r"((R)[1]), "=r"((R)[2]), "=r"((R)[3]) : "r"(ADDR))

__device__ __forceinline__ uint32_t h2u(__half2 h) {
    return *reinterpret_cast<uint32_t*>(&h);
}

// ---------------- kernel 1: layernorm-normalize (fp16 out) + zero accumulators ----------------
__global__ void ln_kernel(const float* __restrict__ x, int nrows) {
    int warp = (blockIdx.x * blockDim.x + threadIdx.x) >> 5;
    int lane = threadIdx.x & 31;
    if (warp >= nrows) return;
    const float4* x4 = reinterpret_cast<const float4*>(x);
    float4 v = x4[warp * 32 + lane];
    float s = v.x + v.y + v.z + v.w;
    #pragma unroll
    for (int o = 16; o > 0; o >>= 1) s += __shfl_xor_sync(0xffffffffu, s, o);
    float mu = s * (1.0f / 128.0f);
    float4 d = make_float4(v.x - mu, v.y - mu, v.z - mu, v.w - mu);
    float ss = d.x*d.x + d.y*d.y + d.z*d.z + d.w*d.w;
    #pragma unroll
    for (int o = 16; o > 0; o >>= 1) ss += __shfl_xor_sync(0xffffffffu, ss, o);
    float rs = rsqrtf(ss * (1.0f / 128.0f) + 1e-5f);
    uint2 o2;
    o2.x = h2u(__floats2half2_rn(d.x * rs, d.y * rs));
    o2.y = h2u(__floats2half2_rn(d.z * rs, d.w * rs));
    reinterpret_cast<uint2*>(g_lnH)[warp * 32 + lane] = o2;
    uint2 z = make_uint2(0u, 0u);
    reinterpret_cast<uint2*>(g_AH )[warp * 32 + lane] = z;
    reinterpret_cast<uint2*>(g_ArH)[warp * 32 + lane] = z;
    if (lane == 0) { g_din[warp] = 0.f; g_dout[warp] = 0.f; }
}

// ---------------- kernel 2a: degree count ----------------
__global__ void deg_kernel(const int* __restrict__ src, const int* __restrict__ dst,
                           int n_edges) {
    int e = blockIdx.x * blockDim.x + threadIdx.x;
    if (e >= n_edges) return;
    atomicAdd(&g_din [dst[e]], 1.0f);
    atomicAdd(&g_dout[src[e]], 1.0f);
}

// ---------------- kernel 2b: edge scatter (fp16, both dirs in one warp) ----------------
// lanes 0-15:  g_AH[d]  += ln[s] / din[d]    (16B per lane)
// lanes 16-31: g_ArH[s] += ln[d] / dout[s]
__global__ void scatter_kernel(const int* __restrict__ src, const int* __restrict__ dst,
                               int n_edges) {
    int e = (blockIdx.x * blockDim.x + threadIdx.x) >> 5;
    int lane = threadIdx.x & 31;
    if (e >= n_edges) return;
    int s = src[e];
    int d = dst[e];
    int rev = lane >> 4;            // 0 fwd, 1 rev
    int c   = lane & 15;            // 16B chunk index within the 256B row
    int nld = rev ? d : s;          // node to read ln from
    int nst = rev ? s : d;          // node accumulator to update
    float cntv = rev ? g_dout[s] : g_din[d];    // >= 1 by construction
    __half2 sc = __float2half2_rn(__frcp_rn(cntv));

    uint4 v = reinterpret_cast<const uint4*>(g_lnH)[nld * 16 + c];
    __half2* h = reinterpret_cast<__half2*>(&v);
    h[0] = __hmul2(h[0], sc);
    h[1] = __hmul2(h[1], sc);
    h[2] = __hmul2(h[2], sc);
    h[3] = __hmul2(h[3], sc);

    __half* base = rev ? g_ArH : g_AH;
    __half* p = base + nst * DIM + c * 8;
    asm volatile("red.global.add.noftz.v4.f16x2 [%0], {%1,%2,%3,%4};"
                 :: "l"(p), "r"(v.x), "r"(v.y), "r"(v.z), "r"(v.w) : "memory");
}

// ---------------- kernel 3: merged bidirectional SAGE GEMM (fp16 mma, fp32 acc) ----------------
// One kernel computes BOTH directions:
//   z0 = ln@(Ws0 g0)^T + A @(Wn0 g0)^T ; z1 = ln@(Ws1 g1)^T + Ar@(Wn1 g1)^T
//   out = x + relu(z0 + bias0 + m0*cn0) + relu(z1 + bias1 + m1*cn1)
// Block tile 128x128, 16 warps (4x4), warp tile 32x32 per direction.
// sB holds 4 weight matrices: [Ws0g0 | Wn0g0 | Ws1g1 | Wn1g1], k = 0..511.
#define GTPB   512
#define MTILE  128
#define SB_H   520            // halves: 512 + 8 pad (260 words, mod 32 = 4 -> conflict-free)
#define SA_H   40             // halves: 32 + 8 pad  (conflict-free ldmatrix)
#define SB_BYTES (128 * SB_H * 2)             // 133120
#define SA_BYTES (MTILE * SA_H * 2)           // 10240
#define GEMM_SMEM (SB_BYTES + 2 * SA_BYTES + 4 * 128 * 4)

__global__ __launch_bounds__(GTPB, 1) void gemm_kernel(
    const float* __restrict__ gamma,   const float* __restrict__ beta,
    const float* __restrict__ Wself,   const float* __restrict__ Wneigh,
    const float* __restrict__ bias,
    const float* __restrict__ gamma_r, const float* __restrict__ beta_r,
    const float* __restrict__ Wself_r, const float* __restrict__ Wneigh_r,
    const float* __restrict__ bias_r,
    const float* __restrict__ x, float* __restrict__ out,
    int nrows)
{
    extern __shared__ char smem[];
    __half* sBh   = reinterpret_cast<__half*>(smem);
    __half* sA0h  = reinterpret_cast<__half*>(smem + SB_BYTES);
    __half* sA1h  = reinterpret_cast<__half*>(smem + SB_BYTES + SA_BYTES);
    float*  sb0   = reinterpret_cast<float*>(smem + SB_BYTES + 2 * SA_BYTES); // b + Ws0@beta0
    float*  sc0   = sb0 + 128;                                                // Wn0@beta0
    float*  sb1   = sb0 + 256;                                                // b_r + Ws1@beta1
    float*  sc1   = sb0 + 384;                                                // Wn1@beta1

    const uint4* lnv  = reinterpret_cast<const uint4*>(g_lnH);
    const uint4* aggF = reinterpret_cast<const uint4*>(g_AH);
    const uint4* aggR = reinterpret_cast<const uint4*>(g_ArH);

    int tid  = threadIdx.x;
    int lane = tid & 31;
    int warp = tid >> 5;
    int wm = warp >> 2;          // 0..3 : 32-row slab
    int wn = warp & 3;           // 0..3 : 32-col slab
    int t = lane & 3, g = lane >> 2;

    uint32_t sA0u = (uint32_t)__cvta_generic_to_shared(sA0h);
    uint32_t sA1u = (uint32_t)__cvta_generic_to_shared(sA1h);

    // ---- stage 4 weight matrices, gamma folded, fp16 ----
    {
        const float4* mats[4] = {
            reinterpret_cast<const float4*>(Wself),
            reinterpret_cast<const float4*>(Wneigh),
            reinterpret_cast<const float4*>(Wself_r),
            reinterpret_cast<const float4*>(Wneigh_r) };
        const float4* gms[4] = {
            reinterpret_cast<const float4*>(gamma),
            reinterpret_cast<const float4*>(gamma),
            reinterpret_cast<const float4*>(gamma_r),
            reinterpret_cast<const float4*>(gamma_r) };
        #pragma unroll
        for (int w = 0; w < 4; w++) {
            const float4* W4 = mats[w];
            const float4* G4 = gms[w];
            int koff = w * 128;
            #pragma unroll
            for (int j = 0; j < 8; j++) {
                int idx = tid + j * GTPB;       // 4096 float4 per matrix
                int n = idx >> 5, c4 = idx & 31;
                float4 v  = W4[n * 32 + c4];
                float4 gm = G4[c4];
                uint2 o;
                o.x = h2u(__floats2half2_rn(v.x * gm.x, v.y * gm.y));
                o.y = h2u(__floats2half2_rn(v.z * gm.z, v.w * gm.w));
                *reinterpret_cast<uint2*>(sBh + n * SB_H + koff + c4 * 4) = o;
            }
        }
    }
    // ---- bias terms (fp32) ----
    if (tid < 128) {
        const float4* b0v = reinterpret_cast<const float4*>(beta);
        const float4* b1v = reinterpret_cast<const float4*>(beta_r);
        const float4* W0s = reinterpret_cast<const float4*>(Wself);
        const float4* W0n = reinterpret_cast<const float4*>(Wneigh);
        const float4* W1s = reinterpret_cast<const float4*>(Wself_r);
        const float4* W1n = reinterpret_cast<const float4*>(Wneigh_r);
        float a0 = 0.f, a1 = 0.f, a2 = 0.f, a3 = 0.f;
        #pragma unroll 4
        for (int k4 = 0; k4 < 32; k4++) {
            float4 p0 = b0v[k4], p1 = b1v[k4];
            float4 q0 = W0s[tid * 32 + k4];
            float4 q1 = W0n[tid * 32 + k4];
            float4 q2 = W1s[tid * 32 + k4];
            float4 q3 = W1n[tid * 32 + k4];
            a0 += p0.x*q0.x + p0.y*q0.y + p0.z*q0.z + p0.w*q0.w;
            a1 += p0.x*q1.x + p0.y*q1.y + p0.z*q1.z + p0.w*q1.w;
            a2 += p1.x*q2.x + p1.y*q2.y + p1.z*q2.z + p1.w*q2.w;
            a3 += p1.x*q3.x + p1.y*q3.y + p1.z*q3.z + p1.w*q3.w;
        }
        sb0[tid] = bias[tid]   + a0;
        sc0[tid] = a1;
        sb1[tid] = bias_r[tid] + a2;
        sc1[tid] = a3;
    }
    __syncthreads();

// chunk C (0..11): 32 k-halves; 0-3 from ln, 4-7 from A (fwd), 8-11 from Ar (rev).
// Tile row = 64B -> 4 x 16B cp.async, 512 threads cover 128 rows x 4 chunks.
#define ISSUE_CHUNK(C, DSTU) do {                                              \
    const uint4* srcb = ((C) < 4) ? lnv : (((C) < 8) ? aggF : aggR);           \
    int c16 = (((C) < 4) ? (C) : (((C) < 8) ? (C) - 4 : (C) - 8)) * 4;         \
    int row = tid >> 2, c8 = tid & 3;                                          \
    int gr = row0 + row;                                                       \
    const uint4* gp = srcb + (size_t)gr * 16 + c16 + c8;                       \
    uint32_t da = (DSTU) + row * (SA_H * 2) + c8 * 16;                         \
    int sz = (gr < nrows) ? 16 : 0;                                            \
    asm volatile("cp.async.cg.shared.global [%0], [%1], 16, %2;"               \
                 :: "r"(da), "l"(gp), "r"(sz));                                \
} while (0)

// one k=16 slice against weight block column KB -> ACC
#define MMA_STEP(ACC, KB) do {                                                 \
    uint32_t bf[4][2];                                                         \
    _Pragma("unroll")                                                          \
    for (int ni = 0; ni < 4; ni++) {                                           \
        const __half* bb = sBh + (wn * 32 + ni * 8 + g) * SB_H + (KB) + 2 * t; \
        bf[ni][0] = *reinterpret_cast<const uint32_t*>(bb);                    \
        bf[ni][1] = *reinterpret_cast<const uint32_t*>(bb + 8);                \
    }                                                                          \
    _Pragma("unroll")                                                          \
    for (int mi = 0; mi < 2; mi++)                                             \
        _Pragma("unroll")                                                      \
        for (int ni = 0; ni < 4; ni++)                                         \
            mma_f16(ACC[mi][ni], af[mi], bf[ni]);                              \
} while (0)

    int ntiles = (nrows + MTILE - 1) / MTILE;
    for (int tile = blockIdx.x; tile < ntiles; tile += gridDim.x) {
        int row0 = tile * MTILE;

        float acc0[2][4][4], acc1[2][4][4];
        #pragma unroll
        for (int mi = 0; mi < 2; mi++)
            #pragma unroll
            for (int ni = 0; ni < 4; ni++)
                #pragma unroll
                for (int q = 0; q < 4; q++) { acc0[mi][ni][q] = 0.f; acc1[mi][ni][q] = 0.f; }

        ISSUE_CHUNK(0, sA0u);
        asm volatile("cp.async.commit_group;" ::: "memory");

        #pragma unroll 1
        for (int c = 0; c < 12; c++) {
            uint32_t curu = (c & 1) ? sA1u : sA0u;
            uint32_t nxtu = (c & 1) ? sA0u : sA1u;
            if (c < 11) {
                ISSUE_CHUNK(c + 1, nxtu);
                asm volatile("cp.async.commit_group;" ::: "memory");
                asm volatile("cp.async.wait_group 1;" ::: "memory");
            } else {
                asm volatile("cp.async.wait_group 0;" ::: "memory");
            }
            __syncthreads();
            #pragma unroll
            for (int ks = 0; ks < 2; ks++) {
                uint32_t af[2][4];
                #pragma unroll
                for (int mi = 0; mi < 2; mi++) {
                    uint32_t ad = curu +
                        ((wm * 32 + mi * 16 + (lane & 15)) * SA_H + ks * 16 + (lane >> 4) * 8) * 2;
                    LDSM4(af[mi], ad);
                }
                if (c < 4) {                       // ln chunk: feeds BOTH directions
                    MMA_STEP(acc0, c * 32 + ks * 16);
                    MMA_STEP(acc1, 256 + c * 32 + ks * 16);
                } else if (c < 8) {                // A chunk -> dir 0
                    MMA_STEP(acc0, 128 + (c - 4) * 32 + ks * 16);
                } else {                           // Ar chunk -> dir 1
                    MMA_STEP(acc1, 384 + (c - 8) * 32 + ks * 16);
                }
            }
            __syncthreads();
        }

        // ---- epilogue: out = x + relu(z0) + relu(z1) ----
        const float2* add2 = reinterpret_cast<const float2*>(x);
        float2*       out2 = reinterpret_cast<float2*>(out);
        #pragma unroll
        for (int mi = 0; mi < 2; mi++) {
            int r1 = row0 + wm * 32 + mi * 16 + g;
            int r2 = r1 + 8;
            float m01 = (r1 < nrows && g_din [r1] > 0.f) ? 1.f : 0.f;
            float m02 = (r2 < nrows && g_din [r2] > 0.f) ? 1.f : 0.f;
            float m11 = (r1 < nrows && g_dout[r1] > 0.f) ? 1.f : 0.f;
            float m12 = (r2 < nrows && g_dout[r2] > 0.f) ? 1.f : 0.f;
            #pragma unroll
            for (int ni = 0; ni < 4; ni++) {
                int col = wn * 32 + ni * 8 + t * 2;
                float b00 = sb0[col], b01 = sb0[col + 1];
                float c00 = sc0[col], c01 = sc0[col + 1];
                float b10 = sb1[col], b11 = sb1[col + 1];
                float c10 = sc1[col], c11 = sc1[col + 1];
                if (r1 < nrows) {
                    int e = (r1 * DIM + col) >> 1;
                    float2 a = add2[e];
                    float z0x = acc0[mi][ni][0] + b00 + m01 * c00;
                    float z0y = acc0[mi][ni][1] + b01 + m01 * c01;
                    float z1x = acc1[mi][ni][0] + b10 + m11 * c10;
                    float z1y = acc1[mi][ni][1] + b11 + m11 * c11;
                    float2 o;
                    o.x = a.x + fmaxf(z0x, 0.f) + fmaxf(z1x, 0.f);
                    o.y = a.y + fmaxf(z0y, 0.f) + fmaxf(z1y, 0.f);
                    out2[e] = o;
                }
                if (r2 < nrows) {
                    int e = (r2 * DIM + col) >> 1;
                    float2 a = add2[e];
                    float z0x = acc0[mi][ni][2] + b00 + m02 * c00;
                    float z0y = acc0[mi][ni][3] + b01 + m02 * c01;
                    float z1x = acc1[mi][ni][2] + b10 + m12 * c10;
                    float z1y = acc1[mi][ni][3] + b11 + m12 * c11;
                    float2 o;
                    o.x = a.x + fmaxf(z0x, 0.f) + fmaxf(z1x, 0.f);
                    o.y = a.y + fmaxf(z0y, 0.f) + fmaxf(z1y, 0.f);
                    out2[e] = o;
                }
            }
        }
    }
#undef ISSUE_CHUNK
#undef MMA_STEP
}

// ---------------- launch ----------------
extern "C" void kernel_launch(void* const* d_in, const int* in_sizes, int n_in,
                              void* d_out, int out_size)
{
    const float* x       = (const float*)d_in[0];
    const int*   src     = (const int*)  d_in[1];
    const int*   dst     = (const int*)  d_in[2];
    const float* gamma   = (const float*)d_in[3];
    const float* beta    = (const float*)d_in[4];
    const float* Wself   = (const float*)d_in[5];
    const float* Wneigh  = (const float*)d_in[6];
    const float* b       = (const float*)d_in[7];
    const float* gamma_r = (const float*)d_in[8];
    const float* beta_r  = (const float*)d_in[9];
    const float* Wself_r = (const float*)d_in[10];
    const float* Wneigh_r= (const float*)d_in[11];
    const float* b_r     = (const float*)d_in[12];
    float* out = (float*)d_out;

    int N = in_sizes[0] / DIM;       // 100000
    int E = in_sizes[1];             // 640000

    // 1) normalize (fp16) + zero accumulators/degrees
    ln_kernel<<<(N + 7) / 8, 256>>>(x, N);
    // 2a) degree count
    deg_kernel<<<(E + 255) / 256, 256>>>(src, dst, E);
    // 2b) edge scatter (both directions, fp16 vector red; 1/deg via rcp)
    scatter_kernel<<<(E + 7) / 8, 256>>>(src, dst, E);
    // 3) merged bidirectional GEMM
    cudaFuncSetAttribute(gemm_kernel, cudaFuncAttributeMaxDynamicSharedMemorySize, GEMM_SMEM);
    int ntiles = (N + MTILE - 1) / MTILE;
    int gblocks = ntiles < 148 ? ntiles : 148;
    gemm_kernel<<<gblocks, GTPB, GEMM_SMEM>>>(gamma, beta, Wself, Wneigh, b,
                                              gamma_r, beta_r, Wself_r, Wneigh_r, b_r,
                                              x, out, N);
}